// round 12
// baseline (speedup 1.0000x reference)
#include <cuda_runtime.h>
#include <math.h>

#define SEQ 4096
#define HID 1024
#define FH  4096   // 4*HID
#define NB  128    // scan blocks
#define FPAD 32    // flag padding: 32 uints = 128 B = one L2 line per flag

// Scratch (no cudaMalloc allowed)
__device__ float g_xg[(size_t)SEQ * FH];
__device__ float g_hbuf[2][HID];
__device__ unsigned int g_flag[NB * FPAD];   // one flag per 128B line

// ---------------- packed f32x2 helpers (sm_103a) ----------------
__device__ __forceinline__ unsigned long long pk2(float x, float y) {
    unsigned long long r;
    asm("mov.b64 %0, {%1, %2};" : "=l"(r) : "f"(x), "f"(y));
    return r;
}
__device__ __forceinline__ void upk2(unsigned long long v, float& x, float& y) {
    asm("mov.b64 {%0, %1}, %2;" : "=f"(x), "=f"(y) : "l"(v));
}
__device__ __forceinline__ unsigned long long fma2(
    unsigned long long a, unsigned long long b, unsigned long long c) {
    unsigned long long d;
    asm("fma.rn.f32x2 %0, %1, %2, %3;" : "=l"(d) : "l"(a), "l"(b), "l"(c));
    return d;
}

__device__ __forceinline__ unsigned int ld_acq(const unsigned int* p) {
    unsigned int v;
    asm volatile("ld.acquire.gpu.global.u32 %0, [%1];" : "=r"(v) : "l"(p));
    return v;
}
__device__ __forceinline__ void st_rel(unsigned int* p, unsigned int v) {
    asm volatile("st.release.gpu.global.u32 [%0], %1;" :: "l"(p), "r"(v) : "memory");
}

// ---------------------------------------------------------------------------
// Kernel A: xg[s][r] = dot(emb[tok[s]], W_ih[r]) + b_ih[r] + b_hh[r]
// ---------------------------------------------------------------------------
__global__ __launch_bounds__(256) void xg_gemm(
    const int* __restrict__ tok, const float* __restrict__ emb,
    const float* __restrict__ Wih, const float* __restrict__ bih,
    const float* __restrict__ bhh)
{
    __shared__ float As[2][8][128];
    __shared__ float Bs[2][8][128];
    __shared__ int toks[128];

    const int tid = threadIdx.x;
    const int tx = tid & 15, ty = tid >> 4;
    const int s0 = blockIdx.y * 128;
    const int r0 = blockIdx.x * 128;

    if (tid < 128) toks[tid] = tok[s0 + tid];
    __syncthreads();

    unsigned long long acc2[8][4];
#pragma unroll
    for (int i = 0; i < 8; i++)
#pragma unroll
        for (int jp = 0; jp < 4; jp++) acc2[i][jp] = pk2(0.f, 0.f);

    const int lrow = tid >> 1;
    const int kq = (tid & 1) * 4;
    const size_t arow = (size_t)toks[lrow] * HID + kq;
    const size_t brow = (size_t)(r0 + lrow) * HID + kq;

    float4 av = *(const float4*)(emb + arow);
    float4 bv = *(const float4*)(Wih + brow);

    int buf = 0;
    for (int k0 = 0; k0 < HID; k0 += 8) {
        As[buf][kq + 0][lrow] = av.x; As[buf][kq + 1][lrow] = av.y;
        As[buf][kq + 2][lrow] = av.z; As[buf][kq + 3][lrow] = av.w;
        Bs[buf][kq + 0][lrow] = bv.x; Bs[buf][kq + 1][lrow] = bv.y;
        Bs[buf][kq + 2][lrow] = bv.z; Bs[buf][kq + 3][lrow] = bv.w;
        __syncthreads();
        if (k0 + 8 < HID) {
            av = *(const float4*)(emb + arow + k0 + 8);
            bv = *(const float4*)(Wih + brow + k0 + 8);
        }
#pragma unroll
        for (int kk = 0; kk < 8; kk++) {
            float4 alo = *(const float4*)&As[buf][kk][ty * 4];
            float4 ahi = *(const float4*)&As[buf][kk][64 + ty * 4];
            float4 blo = *(const float4*)&Bs[buf][kk][tx * 4];
            float4 bhi = *(const float4*)&Bs[buf][kk][64 + tx * 4];
            unsigned long long b2[4] = {
                pk2(blo.x, blo.y), pk2(blo.z, blo.w),
                pk2(bhi.x, bhi.y), pk2(bhi.z, bhi.w)};
            float a[8] = {alo.x, alo.y, alo.z, alo.w,
                          ahi.x, ahi.y, ahi.z, ahi.w};
#pragma unroll
            for (int i = 0; i < 8; i++) {
                unsigned long long ad = pk2(a[i], a[i]);
#pragma unroll
                for (int jp = 0; jp < 4; jp++)
                    acc2[i][jp] = fma2(ad, b2[jp], acc2[i][jp]);
            }
        }
        buf ^= 1;
    }

    float4 bl1 = *(const float4*)(bih + r0 + tx * 4);
    float4 bl2 = *(const float4*)(bhh + r0 + tx * 4);
    float4 bh1 = *(const float4*)(bih + r0 + 64 + tx * 4);
    float4 bh2 = *(const float4*)(bhh + r0 + 64 + tx * 4);
    float4 biasl = {bl1.x + bl2.x, bl1.y + bl2.y, bl1.z + bl2.z, bl1.w + bl2.w};
    float4 biash = {bh1.x + bh2.x, bh1.y + bh2.y, bh1.z + bh2.z, bh1.w + bh2.w};

#pragma unroll
    for (int i = 0; i < 8; i++) {
        int s = s0 + ((i < 4) ? (ty * 4 + i) : (64 + ty * 4 + i - 4));
        float4 o1, o2;
        upk2(acc2[i][0], o1.x, o1.y); upk2(acc2[i][1], o1.z, o1.w);
        upk2(acc2[i][2], o2.x, o2.y); upk2(acc2[i][3], o2.z, o2.w);
        o1.x += biasl.x; o1.y += biasl.y; o1.z += biasl.z; o1.w += biasl.w;
        o2.x += biash.x; o2.y += biash.y; o2.z += biash.z; o2.w += biash.w;
        *(float4*)(g_xg + (size_t)s * FH + r0 + tx * 4) = o1;
        *(float4*)(g_xg + (size_t)s * FH + r0 + 64 + tx * 4) = o2;
    }
}

// ---------------------------------------------------------------------------
// Kernel B: persistent 128-CTA scan, 256 threads, one warp per unit.
// R9: each thread polls ONLY its dependency's flag (block tid>>1), stages its
// h slice immediately (no poll barrier). Flags padded to one L2 line each.
// ---------------------------------------------------------------------------
__global__ __launch_bounds__(256, 1) void lstm_scan(
    const float* __restrict__ Whh, const float* __restrict__ h0,
    const float* __restrict__ c0)
{
    __shared__ float sh[32][33];     // h staged: h[k] at sh[k&31][k>>5]
    const int tid  = threadIdx.x;
    const int wid  = tid >> 5;       // unit within block (0..7)
    const int lane = tid & 31;
    const int j    = blockIdx.x * 8 + wid;

    // Preload W_hh rows {i,f,g,o} for unit j, k in [lane*32, lane*32+32)
    unsigned long long w2[4][16];
#pragma unroll
    for (int gate = 0; gate < 4; gate++) {
        const float4* p =
            (const float4*)(Whh + ((size_t)(gate * HID + j)) * HID + lane * 32);
#pragma unroll
        for (int q = 0; q < 8; q++) {
            float4 v = __ldg(p + q);
            w2[gate][2 * q + 0] = pk2(v.x, v.y);
            w2[gate][2 * q + 1] = pk2(v.z, v.w);
        }
    }

    float cst = (lane == 0) ? __ldg(c0 + j) : 0.f;
    const float nl_scale = (lane == 2) ? 2.f : 1.f;   // tanh lane via sig(2x)

    // This thread stages h elements k = tid*4 .. tid*4+3 (producer block tid>>1)
    const int kbase = tid * 4;
    const int col   = tid >> 3;
    const unsigned int* depflag = &g_flag[(tid >> 1) * FPAD];

    for (int t = 0; t < SEQ; t++) {
        // xg prefetch (independent of h): lanes 0..3 fetch this unit's gates
        float xr = 0.f;
        if (lane < 4)
            xr = __ldg(g_xg + (size_t)t * FH + lane * HID + j);

        if (t == 0) {
            float4 hv = *((const float4*)h0 + tid);
            sh[(kbase + 0) & 31][col] = hv.x;
            sh[(kbase + 1) & 31][col] = hv.y;
            sh[(kbase + 2) & 31][col] = hv.z;
            sh[(kbase + 3) & 31][col] = hv.w;
        } else {
            // wait only for the producer of THIS thread's h slice
            while (ld_acq(depflag) < (unsigned int)t) { }
            float4 hv = __ldcg((const float4*)g_hbuf[(t - 1) & 1] + tid);
            sh[(kbase + 0) & 31][col] = hv.x;
            sh[(kbase + 1) & 31][col] = hv.y;
            sh[(kbase + 2) & 31][col] = hv.z;
            sh[(kbase + 3) & 31][col] = hv.w;
        }
        __syncthreads();

        // Mat-vec: thread covers k = lane*32 .. +31; h[lane*32+i] = sh[i][lane]
        unsigned long long a0 = pk2(0.f, 0.f), a1 = a0, a2 = a0, a3 = a0;
#pragma unroll
        for (int q = 0; q < 16; q++) {
            unsigned long long h2 = pk2(sh[2 * q][lane], sh[2 * q + 1][lane]);
            a0 = fma2(w2[0][q], h2, a0);
            a1 = fma2(w2[1][q], h2, a1);
            a2 = fma2(w2[2][q], h2, a2);
            a3 = fma2(w2[3][q], h2, a3);
        }
        float acc[4];
        { float x, y; upk2(a0, x, y); acc[0] = x + y;
          upk2(a1, x, y); acc[1] = x + y;
          upk2(a2, x, y); acc[2] = x + y;
          upk2(a3, x, y); acc[3] = x + y; }
#pragma unroll
        for (int off = 16; off >= 1; off >>= 1) {
            acc[0] += __shfl_xor_sync(0xffffffffu, acc[0], off);
            acc[1] += __shfl_xor_sync(0xffffffffu, acc[1], off);
            acc[2] += __shfl_xor_sync(0xffffffffu, acc[2], off);
            acc[3] += __shfl_xor_sync(0xffffffffu, acc[3], off);
        }

        // lanes 0..3 compute the four gate activations in parallel
        float act = 0.f;
        if (lane < 4) {
            float p = acc[lane] + xr;
            float s = 1.f / (1.f + __expf(-nl_scale * p));
            act = (lane == 2) ? (2.f * s - 1.f) : s;
        }
        float iv = __shfl_sync(0xffffffffu, act, 0);
        float fv = __shfl_sync(0xffffffffu, act, 1);
        float gv = __shfl_sync(0xffffffffu, act, 2);
        float ov = __shfl_sync(0xffffffffu, act, 3);
        if (lane == 0) {
            cst = fv * cst + iv * gv;
            float s2 = 1.f / (1.f + __expf(-2.f * cst));
            g_hbuf[t & 1][j] = ov * (2.f * s2 - 1.f);
        }
        __syncthreads();   // all units' h stores done; also guards sh[] reuse
        if (tid == 0)
            st_rel(&g_flag[blockIdx.x * FPAD], (unsigned int)(t + 1));
    }
}

// ---------------------------------------------------------------------------
// Kernel C: reset flags so the captured graph replays deterministically.
// ---------------------------------------------------------------------------
__global__ __launch_bounds__(1024) void reset_flags_k() {
    for (int i = threadIdx.x; i < NB * FPAD; i += 1024)
        g_flag[i] = 0u;
}

// ---------------------------------------------------------------------------
// Kernel D: out = log_softmax(h_final)
// ---------------------------------------------------------------------------
__global__ __launch_bounds__(1024) void logsoftmax_k(float* __restrict__ out)
{
    __shared__ float red[32];
    __shared__ float s_m, s_s;
    const int tid = threadIdx.x;
    float x = g_hbuf[(SEQ - 1) & 1][tid];

    float m = x;
#pragma unroll
    for (int off = 16; off >= 1; off >>= 1)
        m = fmaxf(m, __shfl_xor_sync(0xffffffffu, m, off));
    if ((tid & 31) == 0) red[tid >> 5] = m;
    __syncthreads();
    if (tid < 32) {
        float v = red[tid];
#pragma unroll
        for (int off = 16; off >= 1; off >>= 1)
            v = fmaxf(v, __shfl_xor_sync(0xffffffffu, v, off));
        if (tid == 0) s_m = v;
    }
    __syncthreads();

    float e = __expf(x - s_m);
    float s = e;
#pragma unroll
    for (int off = 16; off >= 1; off >>= 1)
        s += __shfl_xor_sync(0xffffffffu, s, off);
    if ((tid & 31) == 0) red[tid >> 5] = s;
    __syncthreads();
    if (tid < 32) {
        float v = red[tid];
#pragma unroll
        for (int off = 16; off >= 1; off >>= 1)
            v += __shfl_xor_sync(0xffffffffu, v, off);
        if (tid == 0) s_s = v;
    }
    __syncthreads();

    out[tid] = x - s_m - logf(s_s);
}

// ---------------------------------------------------------------------------
extern "C" void kernel_launch(void* const* d_in, const int* in_sizes, int n_in,
                              void* d_out, int out_size)
{
    const int*   tok = (const int*)  d_in[0];
    const float* emb = (const float*)d_in[1];
    const float* Wih = (const float*)d_in[2];
    const float* Whh = (const float*)d_in[3];
    const float* bih = (const float*)d_in[4];
    const float* bhh = (const float*)d_in[5];
    const float* h0  = (const float*)d_in[6];
    const float* c0  = (const float*)d_in[7];
    float* out = (float*)d_out;

    xg_gemm<<<dim3(FH / 128, SEQ / 128), 256>>>(tok, emb, Wih, bih, bhh);
    lstm_scan<<<NB, 256>>>(Whh, h0, c0);
    reset_flags_k<<<1, 1024>>>();
    logsoftmax_k<<<1, 1024>>>(out);
}

// round 14
// speedup vs baseline: 1.2897x; 1.2897x over previous
#include <cuda_runtime.h>
#include <math.h>

#define SEQ 4096
#define HID 1024
#define FH  4096            // 4*HID
#define NB  128             // blocks (one per SM, persistent)
#define NGEMM 64            // producer threads (2 warps, lowest wid)
#define NSCAN 256           // scan threads (8 warps)
#define NTHR (NGEMM + NSCAN)
#define SCH 128             // s-chunk (steps of xg produced per handshake)
#define NCH (SEQ / SCH)     // 32 chunks
#define KT  64              // k-tile
#define NKT (HID / KT)      // 16 k-tiles

// Scratch (no cudaMalloc allowed)
__device__ float g_xg[(size_t)SEQ * FH];
__device__ float g_hbuf[2][HID];
__device__ unsigned int g_flag[NB * 8];   // R6 layout: 32B stride

// ---------------- packed f32x2 helpers (sm_103a) ----------------
__device__ __forceinline__ unsigned long long pk2(float x, float y) {
    unsigned long long r;
    asm("mov.b64 %0, {%1, %2};" : "=l"(r) : "f"(x), "f"(y));
    return r;
}
__device__ __forceinline__ void upk2(unsigned long long v, float& x, float& y) {
    asm("mov.b64 {%0, %1}, %2;" : "=f"(x), "=f"(y) : "l"(v));
}
__device__ __forceinline__ unsigned long long fma2(
    unsigned long long a, unsigned long long b, unsigned long long c) {
    unsigned long long d;
    asm("fma.rn.f32x2 %0, %1, %2, %3;" : "=l"(d) : "l"(a), "l"(b), "l"(c));
    return d;
}
__device__ __forceinline__ unsigned int ld_acq(const unsigned int* p) {
    unsigned int v;
    asm volatile("ld.acquire.gpu.global.u32 %0, [%1];" : "=r"(v) : "l"(p));
    return v;
}
__device__ __forceinline__ void st_rel(unsigned int* p, unsigned int v) {
    asm volatile("st.release.gpu.global.u32 [%0], %1;" :: "l"(p), "r"(v) : "memory");
}
__device__ __forceinline__ void bar_scan() {     // 8 scan warps
    asm volatile("bar.sync 1, %0;" :: "n"(NSCAN) : "memory");
}
__device__ __forceinline__ void bar_gemm() {     // 2 gemm warps
    asm volatile("bar.sync 2, %0;" :: "n"(NGEMM) : "memory");
}

// ---------------------------------------------------------------------------
// Fused kernel: warps 0-1 produce this block's 32 xg columns (GEMM);
// warps 2-9 run the R6 LSTM scan consuming them via an smem progress counter.
// ---------------------------------------------------------------------------
__global__ __launch_bounds__(NTHR, 1) void lstm_fused(
    const int* __restrict__ tok, const float* __restrict__ emb,
    const float* __restrict__ Wih, const float* __restrict__ Whh,
    const float* __restrict__ bih, const float* __restrict__ bhh,
    const float* __restrict__ h0, const float* __restrict__ c0)
{
    __shared__ float sh[32][33];           // h staged for scan warps
    __shared__ float embT[KT][SCH + 1];    // transposed act tile [k][s]
    __shared__ float2 wt2[KT][17];         // W_ih pairs [k][pair], 16 pairs
    __shared__ int toks[SCH];
    __shared__ int sdone;                  // xg rows produced (volatile access)

    const int tid = threadIdx.x;
    const int b   = blockIdx.x;

    if (tid == 0) *(volatile int*)&sdone = 0;
    __syncthreads();                       // only full-block barrier (init)

    if (tid < NGEMM) {
        // =============== GEMM producer warps (low priority) ===============
        const int tx = tid, wg = tx >> 5, l = tx & 31;

        // per-thread bias pairs for its 8 r-pairs (local r = wg*16 + 2p)
        float2 biasp[8];
#pragma unroll
        for (int p = 0; p < 8; p++) {
            int lr = wg * 16 + 2 * p;
            int gr = ((lr >> 3) << 10) + 8 * b + (lr & 7);
            biasp[p].x = bih[gr] + bhh[gr];
            biasp[p].y = bih[gr + 1] + bhh[gr + 1];
        }

        for (int c = 0; c < NCH; c++) {
            const int s0 = c * SCH;
            for (int i = tx; i < SCH; i += NGEMM) toks[i] = tok[s0 + i];

            unsigned long long acc2[4][8];
#pragma unroll
            for (int i = 0; i < 4; i++)
#pragma unroll
                for (int p = 0; p < 8; p++) acc2[i][p] = 0ull;

            for (int kt = 0; kt < NKT; kt++) {
                const int k0 = kt * KT;
                bar_gemm();   // prev compute done (and toks ready on kt=0)
                // stage activations transposed: embT[k][s]
                for (int idx = tx; idx < SCH * (KT / 4); idx += NGEMM) {
                    int s = idx >> 4, q = idx & 15;
                    float4 v = *(const float4*)(
                        emb + (size_t)toks[s] * HID + k0 + 4 * q);
                    embT[4 * q + 0][s] = v.x; embT[4 * q + 1][s] = v.y;
                    embT[4 * q + 2][s] = v.z; embT[4 * q + 3][s] = v.w;
                }
                // stage W_ih pairs: wt2[k][p] = (row 2p, row 2p+1) at k
                for (int idx = tx; idx < 16 * (KT / 4); idx += NGEMM) {
                    int p = idx >> 4, q = idx & 15;
                    int lr = 2 * p;
                    int gr = ((lr >> 3) << 10) + 8 * b + (lr & 7);
                    const float* w0 = Wih + (size_t)gr * HID + k0 + 4 * q;
                    float4 x = *(const float4*)w0;
                    float4 y = *(const float4*)(w0 + HID);
                    wt2[4 * q + 0][p] = make_float2(x.x, y.x);
                    wt2[4 * q + 1][p] = make_float2(x.y, y.y);
                    wt2[4 * q + 2][p] = make_float2(x.z, y.z);
                    wt2[4 * q + 3][p] = make_float2(x.w, y.w);
                }
                bar_gemm();
                // compute: s = l + 32i, pairs wg*8+p
                for (int kk = 0; kk < KT; kk++) {
                    unsigned long long ad0 = pk2(embT[kk][l],      embT[kk][l]);
                    unsigned long long ad1 = pk2(embT[kk][l + 32], embT[kk][l + 32]);
                    unsigned long long ad2 = pk2(embT[kk][l + 64], embT[kk][l + 64]);
                    unsigned long long ad3 = pk2(embT[kk][l + 96], embT[kk][l + 96]);
#pragma unroll
                    for (int p = 0; p < 8; p++) {
                        float2 bb = wt2[kk][wg * 8 + p];
                        unsigned long long b2 = pk2(bb.x, bb.y);
                        acc2[0][p] = fma2(ad0, b2, acc2[0][p]);
                        acc2[1][p] = fma2(ad1, b2, acc2[1][p]);
                        acc2[2][p] = fma2(ad2, b2, acc2[2][p]);
                        acc2[3][p] = fma2(ad3, b2, acc2[3][p]);
                    }
                }
            }
            // epilogue: write this chunk's xg (pairs are adjacent columns)
#pragma unroll
            for (int i = 0; i < 4; i++) {
                int s = s0 + l + 32 * i;
                float* dst = g_xg + (size_t)s * FH;
#pragma unroll
                for (int p = 0; p < 8; p++) {
                    int lr = wg * 16 + 2 * p;
                    int gr = ((lr >> 3) << 10) + 8 * b + (lr & 7);
                    float x, y; upk2(acc2[i][p], x, y);
                    float2 o = make_float2(x + biasp[p].x, y + biasp[p].y);
                    *(float2*)(dst + gr) = o;
                }
            }
            bar_gemm();
            __threadfence_block();
            if (tx == 0) *(volatile int*)&sdone = s0 + SCH;
        }
        return;   // producer warps retire
    }

    // ====================== scan warps (R6 logic) ======================
    const int st   = tid - NGEMM;
    const int wid  = st >> 5;
    const int lane = st & 31;
    const int j    = b * 8 + wid;

    unsigned long long w2[4][16];
#pragma unroll
    for (int gate = 0; gate < 4; gate++) {
        const float4* p =
            (const float4*)(Whh + ((size_t)(gate * HID + j)) * HID + lane * 32);
#pragma unroll
        for (int q = 0; q < 8; q++) {
            float4 v = __ldg(p + q);
            w2[gate][2 * q + 0] = pk2(v.x, v.y);
            w2[gate][2 * q + 1] = pk2(v.z, v.w);
        }
    }

    float cst = (lane == 0) ? __ldg(c0 + j) : 0.f;
    const float nl_scale = (lane == 2) ? 2.f : 1.f;   // tanh via sig(2x)

    const int kbase = st * 4;
    const int col   = st >> 3;

    for (int t = 0; t < SEQ; t++) {
        // xg prefetch (guarded by producer progress; plain ld — same-SM data)
        float xr = 0.f;
        if (lane < 4) {
            while (*(volatile int*)&sdone < t + 1) { }
            xr = g_xg[(size_t)t * FH + lane * HID + j];
        }

        if (t > 0) {
            if (st < NB) {
                const unsigned int* f = &g_flag[st * 8];
                while (ld_acq(f) < (unsigned int)t) { }
            }
            bar_scan();
        }
        const float* hsrc = (t == 0) ? h0 : g_hbuf[(t - 1) & 1];
        {
            float4 hv = __ldcg((const float4*)hsrc + st);
            sh[(kbase + 0) & 31][col] = hv.x;
            sh[(kbase + 1) & 31][col] = hv.y;
            sh[(kbase + 2) & 31][col] = hv.z;
            sh[(kbase + 3) & 31][col] = hv.w;
        }
        bar_scan();

        unsigned long long a0 = 0ull, a1 = 0ull, a2 = 0ull, a3 = 0ull;
#pragma unroll
        for (int q = 0; q < 16; q++) {
            unsigned long long h2 = pk2(sh[2 * q][lane], sh[2 * q + 1][lane]);
            a0 = fma2(w2[0][q], h2, a0);
            a1 = fma2(w2[1][q], h2, a1);
            a2 = fma2(w2[2][q], h2, a2);
            a3 = fma2(w2[3][q], h2, a3);
        }
        float acc[4];
        { float x, y; upk2(a0, x, y); acc[0] = x + y;
          upk2(a1, x, y); acc[1] = x + y;
          upk2(a2, x, y); acc[2] = x + y;
          upk2(a3, x, y); acc[3] = x + y; }
#pragma unroll
        for (int off = 16; off >= 1; off >>= 1) {
            acc[0] += __shfl_xor_sync(0xffffffffu, acc[0], off);
            acc[1] += __shfl_xor_sync(0xffffffffu, acc[1], off);
            acc[2] += __shfl_xor_sync(0xffffffffu, acc[2], off);
            acc[3] += __shfl_xor_sync(0xffffffffu, acc[3], off);
        }

        float act = 0.f;
        if (lane < 4) {
            float p = acc[lane] + xr;
            float s = 1.f / (1.f + __expf(-nl_scale * p));
            act = (lane == 2) ? (2.f * s - 1.f) : s;
        }
        float iv = __shfl_sync(0xffffffffu, act, 0);
        float fv = __shfl_sync(0xffffffffu, act, 1);
        float gv = __shfl_sync(0xffffffffu, act, 2);
        float ov = __shfl_sync(0xffffffffu, act, 3);
        if (lane == 0) {
            cst = fv * cst + iv * gv;
            float s2 = 1.f / (1.f + __expf(-2.f * cst));
            g_hbuf[t & 1][j] = ov * (2.f * s2 - 1.f);
        }
        bar_scan();   // all units' h stores done
        if (st == 0)
            st_rel(&g_flag[b * 8], (unsigned int)(t + 1));
    }
}

// ---------------------------------------------------------------------------
// reset flags so the captured graph replays deterministically.
// ---------------------------------------------------------------------------
__global__ __launch_bounds__(1024) void reset_flags_k() {
    g_flag[threadIdx.x] = 0u;
}

// ---------------------------------------------------------------------------
// out = log_softmax(h_final)
// ---------------------------------------------------------------------------
__global__ __launch_bounds__(1024) void logsoftmax_k(float* __restrict__ out)
{
    __shared__ float red[32];
    __shared__ float s_m, s_s;
    const int tid = threadIdx.x;
    float x = g_hbuf[(SEQ - 1) & 1][tid];

    float m = x;
#pragma unroll
    for (int off = 16; off >= 1; off >>= 1)
        m = fmaxf(m, __shfl_xor_sync(0xffffffffu, m, off));
    if ((tid & 31) == 0) red[tid >> 5] = m;
    __syncthreads();
    if (tid < 32) {
        float v = red[tid];
#pragma unroll
        for (int off = 16; off >= 1; off >>= 1)
            v = fmaxf(v, __shfl_xor_sync(0xffffffffu, v, off));
        if (tid == 0) s_m = v;
    }
    __syncthreads();

    float e = __expf(x - s_m);
    float s = e;
#pragma unroll
    for (int off = 16; off >= 1; off >>= 1)
        s += __shfl_xor_sync(0xffffffffu, s, off);
    if ((tid & 31) == 0) red[tid >> 5] = s;
    __syncthreads();
    if (tid < 32) {
        float v = red[tid];
#pragma unroll
        for (int off = 16; off >= 1; off >>= 1)
            v += __shfl_xor_sync(0xffffffffu, v, off);
        if (tid == 0) s_s = v;
    }
    __syncthreads();

    out[tid] = x - s_m - logf(s_s);
}

// ---------------------------------------------------------------------------
extern "C" void kernel_launch(void* const* d_in, const int* in_sizes, int n_in,
                              void* d_out, int out_size)
{
    const int*   tok = (const int*)  d_in[0];
    const float* emb = (const float*)d_in[1];
    const float* Wih = (const float*)d_in[2];
    const float* Whh = (const float*)d_in[3];
    const float* bih = (const float*)d_in[4];
    const float* bhh = (const float*)d_in[5];
    const float* h0  = (const float*)d_in[6];
    const float* c0  = (const float*)d_in[7];
    float* out = (float*)d_out;

    lstm_fused<<<NB, NTHR>>>(tok, emb, Wih, Whh, bih, bhh, h0, c0);
    reset_flags_k<<<1, 1024>>>();
    logsoftmax_k<<<1, 1024>>>(out);
}